// round 16
// baseline (speedup 1.0000x reference)
#include <cuda_runtime.h>
#include <math.h>
#include <stdint.h>

#define B_   64
#define S_   512
#define P_   32
#define L_   30
#define H_   768
#define FH_  1024
#define MROWS (B_*P_)   // 2048
#define NCTA 128

// ======================= device scratch (no allocation) =======================
__device__ float g_W23[FH_ * 32];      // W2@W3 (lanes 30/31 garbage, masked)
__device__ float g_Wc[2 * H_ * 32];    // W1@W23
__device__ float g_b23[32];
__device__ float g_bc[32];
__device__ float g_part[NCTA * 5];
__device__ unsigned g_bar1, g_bar2, g_done;

__device__ __forceinline__ uint32_t smem_u32(const void* p) {
    uint32_t a;
    asm("{ .reg .u64 t; cvta.to.shared.u64 t, %1; cvt.u32.u64 %0, t; }"
        : "=r"(a) : "l"(p));
    return a;
}
#define CP16(dst_u32, src_ptr) \
    asm volatile("cp.async.cg.shared.global [%0], [%1], 16;" \
        :: "r"(dst_u32), "l"(src_ptr))
#define CP_COMMIT() asm volatile("cp.async.commit_group;")
#define CP_WAIT0()  asm volatile("cp.async.wait_group 0;")

// deterministic grid barrier: all 128 CTAs co-resident (1 CTA/SM by smem)
__device__ __forceinline__ void grid_barrier(unsigned* ctr) {
    __syncthreads();
    __threadfence();
    if (threadIdx.x == 0) {
        atomicAdd(ctr, 1u);
        while (*(volatile unsigned*)ctr < NCTA) { }
    }
    __syncthreads();
    __threadfence();
}

// ======================= fused 3-stage kernel =======================
// grid 128, 256thr, 180KB dyn smem
__global__ __launch_bounds__(256) void k_fused(
    const float* __restrict__ te, const int* __restrict__ pos,
    const float* __restrict__ labels, const float* __restrict__ pooler,
    const float* __restrict__ W1, const float* __restrict__ b1,
    const float* __restrict__ W2, const float* __restrict__ b2,
    const float* __restrict__ W3, const float* __restrict__ b3,
    float* __restrict__ out, int out_size)
{
    extern __shared__ float s[];
    __shared__ float bpartA[8][32];
    __shared__ float bpartB[4][32];
    __shared__ float wpartB[4][3][32];
    __shared__ float pqs[8][32];
    __shared__ float sml[8][5];
    __shared__ float red[NCTA][5];
    __shared__ unsigned s_done;

    const int tid = threadIdx.x;
    const int wid = tid >> 5, lane = tid & 31;
    const int bx = blockIdx.x;

    // ================= STAGE A: W23 = W2 @ W3 (+b23 on block 0) =================
    {
        float* w3s = s;                     // [512*30 + 8] packed
        float* w2s = s + 512 * 30 + 8;      // [8*512]
        const int row0 = bx * 8;

        const uint32_t sa = smem_u32(w3s);
#pragma unroll
        for (int j = 0; j < 15; j++) {      // 3840 cp16
            int c = tid + j * 256;
            CP16(sa + (uint32_t)c * 16, W3 + c * 4);
        }
        const uint32_t sb = smem_u32(w2s);
        const float* g = W2 + (size_t)row0 * 512;
#pragma unroll
        for (int j = 0; j < 4; j++) {       // 1024 cp16
            int c = tid + j * 256;
            CP16(sb + (uint32_t)c * 16, g + c * 4);
        }
        CP_COMMIT(); CP_WAIT0();
        __syncthreads();

        const float* a = w2s + wid * 512;
        float p0 = 0.f, p1 = 0.f, p2 = 0.f, p3 = 0.f;
#pragma unroll 4
        for (int k = 0; k < 512; k += 16) {
            float4 v0 = *(const float4*)&a[k];
            float4 v1 = *(const float4*)&a[k + 4];
            float4 v2 = *(const float4*)&a[k + 8];
            float4 v3 = *(const float4*)&a[k + 12];
            const float* wz = w3s + k * 30 + lane;
            p0 = fmaf(v0.x, wz[0 * 30], p0);
            p0 = fmaf(v0.y, wz[1 * 30], p0);
            p0 = fmaf(v0.z, wz[2 * 30], p0);
            p0 = fmaf(v0.w, wz[3 * 30], p0);
            p1 = fmaf(v1.x, wz[4 * 30], p1);
            p1 = fmaf(v1.y, wz[5 * 30], p1);
            p1 = fmaf(v1.z, wz[6 * 30], p1);
            p1 = fmaf(v1.w, wz[7 * 30], p1);
            p2 = fmaf(v2.x, wz[8 * 30], p2);
            p2 = fmaf(v2.y, wz[9 * 30], p2);
            p2 = fmaf(v2.z, wz[10 * 30], p2);
            p2 = fmaf(v2.w, wz[11 * 30], p2);
            p3 = fmaf(v3.x, wz[12 * 30], p3);
            p3 = fmaf(v3.y, wz[13 * 30], p3);
            p3 = fmaf(v3.z, wz[14 * 30], p3);
            p3 = fmaf(v3.w, wz[15 * 30], p3);
        }
        g_W23[(row0 + wid) * 32 + lane] = (p0 + p1) + (p2 + p3);

        if (bx == 0) {                      // b23: 8 warps x 64-k partials
            float pacc = 0.f;
            const int kb = wid * 64;
#pragma unroll
            for (int kk = 0; kk < 64; kk++)
                pacc = fmaf(b2[kb + kk], w3s[(kb + kk) * 30 + lane], pacc);
            bpartA[wid][lane] = pacc;
            __syncthreads();
            if (wid == 0) {
                float bacc = (lane < L_) ? b3[lane] : 0.f;
#pragma unroll
                for (int w = 0; w < 8; w++) bacc += bpartA[w][lane];
                g_b23[lane] = bacc;
            }
        }
    }
    grid_barrier(&g_bar1);

    // ================= STAGE B: Wc = W1 @ W23 (+bc on block 1) =================
    {
        float* w23s = s;                    // [1024*32]
        float* w1s  = s + FH_ * 32;         // [12*1024]
        const int row0 = bx * 12;

        const uint32_t sa = smem_u32(w23s);
        const float* g = g_W23;
#pragma unroll
        for (int j = 0; j < 32; j++) {      // 8192 cp16
            int c = tid + j * 256;
            CP16(sa + (uint32_t)c * 16, g + c * 4);
        }
        const uint32_t sb = smem_u32(w1s);
        const float* g1 = W1 + (size_t)row0 * FH_;
#pragma unroll
        for (int j = 0; j < 12; j++) {      // 3072 cp16
            int c = tid + j * 256;
            CP16(sb + (uint32_t)c * 16, g1 + c * 4);
        }
        CP_COMMIT(); CP_WAIT0();
        __syncthreads();

        // 8 warps = 4 row-groups(3 rows) x 2 K-halves
        const int rg = wid & 3, kh = wid >> 2;
        const float* a0 = w1s + (rg * 3 + 0) * FH_ + kh * 512;
        const float* a1 = w1s + (rg * 3 + 1) * FH_ + kh * 512;
        const float* a2 = w1s + (rg * 3 + 2) * FH_ + kh * 512;
        const float* wz0 = w23s + kh * 512 * 32;
        float q0 = 0.f, q1 = 0.f, q2 = 0.f;
#pragma unroll 4
        for (int k = 0; k < 512; k += 4) {
            float4 u = *(const float4*)&a0[k];
            float4 v = *(const float4*)&a1[k];
            float4 t4 = *(const float4*)&a2[k];
            float w0 = wz0[(k + 0) * 32 + lane];
            float w1v = wz0[(k + 1) * 32 + lane];
            float w2v = wz0[(k + 2) * 32 + lane];
            float w3v = wz0[(k + 3) * 32 + lane];
            q0 = fmaf(u.x, w0, q0);  q0 = fmaf(u.y, w1v, q0);
            q0 = fmaf(u.z, w2v, q0); q0 = fmaf(u.w, w3v, q0);
            q1 = fmaf(v.x, w0, q1);  q1 = fmaf(v.y, w1v, q1);
            q1 = fmaf(v.z, w2v, q1); q1 = fmaf(v.w, w3v, q1);
            q2 = fmaf(t4.x, w0, q2);  q2 = fmaf(t4.y, w1v, q2);
            q2 = fmaf(t4.z, w2v, q2); q2 = fmaf(t4.w, w3v, q2);
        }
        if (kh == 1) {
            wpartB[rg][0][lane] = q0;
            wpartB[rg][1][lane] = q1;
            wpartB[rg][2][lane] = q2;
        }
        __syncthreads();
        if (kh == 0) {
            g_Wc[(row0 + rg * 3 + 0) * 32 + lane] = q0 + wpartB[rg][0][lane];
            g_Wc[(row0 + rg * 3 + 1) * 32 + lane] = q1 + wpartB[rg][1][lane];
            g_Wc[(row0 + rg * 3 + 2) * 32 + lane] = q2 + wpartB[rg][2][lane];
        }

        if (bx == 1) {                      // bc: warps 0-3 x 256-k partials
            if (wid < 4) {
                float pacc = 0.f;
                const int kb = wid * 256;
#pragma unroll 8
                for (int kk = 0; kk < 256; kk++)
                    pacc = fmaf(b1[kb + kk], w23s[(kb + kk) * 32 + lane], pacc);
                bpartB[wid][lane] = pacc;
            }
            __syncthreads();
            if (wid == 0) {
                float bacc = __ldcg(&g_b23[lane]);
#pragma unroll
                for (int w = 0; w < 4; w++) bacc += bpartB[w][lane];
                g_bc[lane] = bacc;
            }
        }
    }
    grid_barrier(&g_bar2);

    // ================= STAGE C: gather + pq + logits + loss + final =================
    {
        float* wct = s;                     // [768*32]
        float* as  = s + H_ * 32;           // [16*768]
        const int r0 = bx * 16;
        const int batch = bx >> 1;

        const uint32_t sa = smem_u32(wct);
        const float* g = g_Wc;
#pragma unroll
        for (int j = 0; j < 24; j++) {      // 6144 cp16
            int c = tid + j * 256;
            CP16(sa + (uint32_t)c * 16, g + c * 4);
        }
        const uint32_t sb = smem_u32(as);
#pragma unroll
        for (int j = 0; j < 12; j++) {      // 3072 cp16 (192 per row)
            int c = tid + j * 256;
            int row = c / 192, ch = c % 192;
            const float* src = te + ((size_t)batch * S_ + pos[r0 + row]) * H_ + ch * 4;
            CP16(sb + (uint32_t)(row * H_ + ch * 4) * 4, src);
        }
        CP_COMMIT();

        // pq overlapped with staging (L2 reads via ldcg)
        {
            const float4* wcb = (const float4*)(g_Wc + H_ * 32);
            const float* prow = pooler + (size_t)batch * H_;
            const int kb = wid * 96;
            float pacc = 0.f;
#pragma unroll
            for (int kk = 0; kk < 96; kk += 4) {
                float4 a4 = *(const float4*)&prow[kb + kk];
                // ldcg on the 4 W rows (each row 32 floats = 8 float4; lane selects)
                float w0 = __ldcg(&((const float*)wcb)[(kb + kk + 0) * 32 + lane]);
                float w1 = __ldcg(&((const float*)wcb)[(kb + kk + 1) * 32 + lane]);
                float w2 = __ldcg(&((const float*)wcb)[(kb + kk + 2) * 32 + lane]);
                float w3 = __ldcg(&((const float*)wcb)[(kb + kk + 3) * 32 + lane]);
                pacc = fmaf(a4.x, w0, pacc);
                pacc = fmaf(a4.y, w1, pacc);
                pacc = fmaf(a4.z, w2, pacc);
                pacc = fmaf(a4.w, w3, pacc);
            }
            pqs[wid][lane] = pacc;
        }
        CP_WAIT0();
        __syncthreads();
        float pqv = __ldcg(&g_bc[lane]);
#pragma unroll
        for (int w = 0; w < 8; w++) pqv += pqs[w][lane];   // fixed order

        // 2 rows per warp, 2 k-partials each
        const float* a0 = as + (wid * 2 + 0) * H_;
        const float* a1 = as + (wid * 2 + 1) * H_;
        float p00 = 0.f, p01 = 0.f, p10 = 0.f, p11 = 0.f;
#pragma unroll 4
        for (int k = 0; k < H_; k += 8) {
            float4 u0 = *(const float4*)&a0[k];
            float4 u1 = *(const float4*)&a0[k + 4];
            float4 v0 = *(const float4*)&a1[k];
            float4 v1 = *(const float4*)&a1[k + 4];
            float w0 = wct[(k + 0) * 32 + lane];
            float w1 = wct[(k + 1) * 32 + lane];
            float w2 = wct[(k + 2) * 32 + lane];
            float w3 = wct[(k + 3) * 32 + lane];
            float w4 = wct[(k + 4) * 32 + lane];
            float w5 = wct[(k + 5) * 32 + lane];
            float w6 = wct[(k + 6) * 32 + lane];
            float w7 = wct[(k + 7) * 32 + lane];
            p00 = fmaf(u0.x, w0, p00); p00 = fmaf(u0.y, w1, p00);
            p00 = fmaf(u0.z, w2, p00); p00 = fmaf(u0.w, w3, p00);
            p01 = fmaf(u1.x, w4, p01); p01 = fmaf(u1.y, w5, p01);
            p01 = fmaf(u1.z, w6, p01); p01 = fmaf(u1.w, w7, p01);
            p10 = fmaf(v0.x, w0, p10); p10 = fmaf(v0.y, w1, p10);
            p10 = fmaf(v0.z, w2, p10); p10 = fmaf(v0.w, w3, p10);
            p11 = fmaf(v1.x, w4, p11); p11 = fmaf(v1.y, w5, p11);
            p11 = fmaf(v1.z, w6, p11); p11 = fmaf(v1.w, w7, p11);
        }
        float acc[2] = { p00 + p01, p10 + p11 };

        const bool active = (lane < L_);
        float st0 = 0.f, st1 = 0.f, st2 = 0.f, st3 = 0.f, st4 = 0.f;
#pragma unroll
        for (int r = 0; r < 2; r++) {
            int gr = r0 + wid * 2 + r;
            float x = acc[r] + pqv;
            float y = active ? labels[(size_t)gr * L_ + lane] : -1.0f;

            unsigned ball_bin  = __ballot_sync(0xffffffffu, active && (x > 0.f));
            unsigned ball_one  = __ballot_sync(0xffffffffu, active && (y > 0.5f));
            unsigned ball_real = __ballot_sync(0xffffffffu, active && (y != -1.0f));

            float sp  = fmaxf(x, 0.f) + log1pf(expf(-fabsf(x)));
            float bce = active ? (sp - x * y) : 0.f;
#pragma unroll
            for (int o = 16; o; o >>= 1) bce += __shfl_xor_sync(0xffffffffu, bce, o);

            if (lane == 0) {
                float mf = (ball_real != 0u) ? 1.f : 0.f;
                int co = __popc(ball_bin);
                int cl = __popc(ball_one);
                float cd = (float)(co - cl);
                bool eq = (mf != 0.f) && (co == 1) && (cl == 1);
                float pd = eq ? (float)(__ffs(ball_bin) - __ffs(ball_one)) : 0.f;
                st0 += mf * bce;
                st1 += mf;
                st2 += mf * cd * cd;
                st3 += pd * pd;
                st4 += eq ? 1.f : 0.f;
            }
        }
        if (lane == 0) {
            sml[wid][0] = st0; sml[wid][1] = st1; sml[wid][2] = st2;
            sml[wid][3] = st3; sml[wid][4] = st4;
        }
        __syncthreads();
        if (tid < 5) {
            float ssum = 0.f;
            for (int w = 0; w < 8; w++) ssum += sml[w][tid];   // fixed order
            g_part[bx * 5 + tid] = ssum;
        }

        // ---- last-block final reduction (deterministic fixed-order tree) ----
        __threadfence();
        __syncthreads();
        if (tid == 0) s_done = atomicAdd(&g_done, 1u);
        __syncthreads();
        if (s_done == NCTA - 1) {
            __threadfence();
            if (tid < NCTA)
                for (int c = 0; c < 5; c++) red[tid][c] = g_part[tid * 5 + c];
            __syncthreads();
            for (int st = NCTA / 2; st > 0; st >>= 1) {
                if (tid < st)
                    for (int c = 0; c < 5; c++) red[tid][c] += red[tid + st][c];
                __syncthreads();
            }
            if (tid == 0) {
                float bce_loss   = red[0][0] / (red[0][1] * (float)L_);
                float count_loss = red[0][2] / (float)MROWS;
                float pos_loss   = (red[0][4] > 0.f) ? (red[0][3] / red[0][4]) : 0.f;
                float loss = bce_loss + 10.f * count_loss + 5.f * pos_loss;
                for (int i = 0; i < out_size; i++) out[i] = loss;
                // reset counters for next graph replay
                g_bar1 = 0; g_bar2 = 0; g_done = 0;
            }
        }
    }
}

// ======================= launch =======================
extern "C" void kernel_launch(void* const* d_in, const int* in_sizes, int n_in,
                              void* d_out, int out_size)
{
    const float* te   = (const float*)d_in[0];
    const float* pool = (const float*)d_in[1];
    const int*   pos  = (const int*)  d_in[2];
    const float* lab  = (const float*)d_in[3];
    const float* W1   = (const float*)d_in[4];
    const float* b1   = (const float*)d_in[5];
    const float* W2   = (const float*)d_in[6];
    const float* b2   = (const float*)d_in[7];
    const float* W3   = (const float*)d_in[8];
    const float* b3   = (const float*)d_in[9];

    // max stage footprint: stage B = (1024*32 + 12*1024) * 4 = 180224 B
    const int SM_FUSED = (FH_ * 32 + 12 * FH_) * 4;
    cudaFuncSetAttribute(k_fused, cudaFuncAttributeMaxDynamicSharedMemorySize, SM_FUSED);

    k_fused<<<NCTA, 256, SM_FUSED>>>(te, pos, lab, pool,
                                     W1, b1, W2, b2, W3, b3,
                                     (float*)d_out, out_size);
}

// round 17
// speedup vs baseline: 1.3923x; 1.3923x over previous
#include <cuda_runtime.h>
#include <math.h>
#include <stdint.h>

#define B_   64
#define S_   512
#define P_   32
#define L_   30
#define H_   768
#define FH_  1024
#define MROWS (B_*P_)   // 2048

// ======================= device scratch (no allocation) =======================
__device__ float g_W23[FH_ * 32];      // W2@W3 (lanes 30/31 garbage, masked)
__device__ float g_Wc[2 * H_ * 32];    // W1@W23
__device__ float g_b23[32];
__device__ float g_bc[32];
__device__ float g_part[128 * 5];
__device__ unsigned g_done;

__device__ __forceinline__ uint32_t smem_u32(const void* p) {
    uint32_t a;
    asm("{ .reg .u64 t; cvta.to.shared.u64 t, %1; cvt.u32.u64 %0, t; }"
        : "=r"(a) : "l"(p));
    return a;
}
#define CP16(dst_u32, src_ptr) \
    asm volatile("cp.async.cg.shared.global [%0], [%1], 16;" \
        :: "r"(dst_u32), "l"(src_ptr))
#define CP_COMMIT() asm volatile("cp.async.commit_group;")
#define CP_WAIT0()  asm volatile("cp.async.wait_group 0;")

// ======================= stage 1: W23 = W2 @ W3 (+b23) =======================
// grid 128, 512thr: 16 warps = 8 rows x 16 K-slices (32k each), smem combine
__global__ __launch_bounds__(512) void k_w23(const float* __restrict__ W2,
                                             const float* __restrict__ W3,
                                             const float* __restrict__ b2,
                                             const float* __restrict__ b3) {
    extern __shared__ float s[];
    float* w3s = s;                  // [512*30+8] packed ~60KB
    float* w2s = s + 512 * 30 + 8;   // [8*512] 16KB
    __shared__ float ppart[16][8][32];
    __shared__ float bpart[16][32];
    const int tid = threadIdx.x;
    const int wid = tid >> 5, lane = tid & 31;
    const int row0 = blockIdx.x * 8;

    if (blockIdx.x == 0 && tid == 0) g_done = 0;

    {
        const uint32_t sa = smem_u32(w3s);
#pragma unroll
        for (int j = 0; j < 8; j++) {            // 3840 cp16
            int c = tid + j * 512;
            if (c < 3840) CP16(sa + (uint32_t)c * 16, W3 + c * 4);
        }
        const uint32_t sb = smem_u32(w2s);
        const float* g = W2 + (size_t)row0 * 512;
#pragma unroll
        for (int j = 0; j < 2; j++) {            // 1024 cp16
            int c = tid + j * 512;
            CP16(sb + (uint32_t)c * 16, g + c * 4);
        }
        CP_COMMIT(); CP_WAIT0();
    }
    __syncthreads();

    // warp wid: all 8 rows, K slice [wid*32, wid*32+32)
    const int kb = wid * 32;
    float acc[8];
#pragma unroll
    for (int r = 0; r < 8; r++) acc[r] = 0.f;
#pragma unroll
    for (int k = 0; k < 32; k += 4) {
        float w0 = w3s[(kb + k + 0) * 30 + lane];
        float w1 = w3s[(kb + k + 1) * 30 + lane];
        float w2v = w3s[(kb + k + 2) * 30 + lane];
        float w3v = w3s[(kb + k + 3) * 30 + lane];
#pragma unroll
        for (int r = 0; r < 8; r++) {
            float4 u = *(const float4*)&w2s[r * 512 + kb + k];
            acc[r] = fmaf(u.x, w0, acc[r]);
            acc[r] = fmaf(u.y, w1, acc[r]);
            acc[r] = fmaf(u.z, w2v, acc[r]);
            acc[r] = fmaf(u.w, w3v, acc[r]);
        }
    }
#pragma unroll
    for (int r = 0; r < 8; r++) ppart[wid][r][lane] = acc[r];
    __syncthreads();
    if (wid < 8) {                               // warp = row, combine 16 slices
        float v = ppart[0][wid][lane];
#pragma unroll
        for (int j = 1; j < 16; j++) v += ppart[j][wid][lane];   // fixed order
        g_W23[(row0 + wid) * 32 + lane] = v;
    }

    if (blockIdx.x == 0) {
        float pacc = 0.f;
        const int kbb = wid * 32;
#pragma unroll
        for (int kk = 0; kk < 32; kk++)
            pacc = fmaf(b2[kbb + kk], w3s[(kbb + kk) * 30 + lane], pacc);
        bpart[wid][lane] = pacc;
        __syncthreads();
        if (wid == 0) {
            float bacc = (lane < L_) ? b3[lane] : 0.f;
#pragma unroll
            for (int w = 0; w < 16; w++) bacc += bpart[w][lane];
            g_b23[lane] = bacc;
        }
    }
}

// ======================= stage 2: Wc = W1 @ W23 (+bc) =======================
// grid 128, 256thr: 8 warps = 12 rows x 8 K-slices (128k each), smem combine
__global__ __launch_bounds__(256) void k_wc(const float* __restrict__ W1,
                                            const float* __restrict__ b1) {
    extern __shared__ float s[];
    float* w23s = s;                  // [1024*32] 128KB
    float* w1s  = s + FH_ * 32;       // [12*1024]  48KB
    __shared__ float ppart[8][12][32];
    __shared__ float bpart[4][32];
    const int tid = threadIdx.x;
    const int wid = tid >> 5, lane = tid & 31;
    const int row0 = blockIdx.x * 12;

    {
        const uint32_t sa = smem_u32(w23s);
        const float* g = g_W23;
#pragma unroll
        for (int j = 0; j < 32; j++) {           // 8192 cp16
            int c = tid + j * 256;
            CP16(sa + (uint32_t)c * 16, g + c * 4);
        }
        const uint32_t sb = smem_u32(w1s);
        const float* g1 = W1 + (size_t)row0 * FH_;
#pragma unroll
        for (int j = 0; j < 12; j++) {           // 3072 cp16
            int c = tid + j * 256;
            CP16(sb + (uint32_t)c * 16, g1 + c * 4);
        }
        CP_COMMIT(); CP_WAIT0();
    }
    __syncthreads();

    // warp wid: all 12 rows, K slice [wid*128, wid*128+128)
    const int kb = wid * 128;
    float acc[12];
#pragma unroll
    for (int r = 0; r < 12; r++) acc[r] = 0.f;
#pragma unroll 2
    for (int k = 0; k < 128; k += 4) {
        float w0 = w23s[(kb + k + 0) * 32 + lane];
        float w1 = w23s[(kb + k + 1) * 32 + lane];
        float w2 = w23s[(kb + k + 2) * 32 + lane];
        float w3 = w23s[(kb + k + 3) * 32 + lane];
#pragma unroll
        for (int r = 0; r < 12; r++) {
            float4 u = *(const float4*)&w1s[r * FH_ + kb + k];
            acc[r] = fmaf(u.x, w0, acc[r]);
            acc[r] = fmaf(u.y, w1, acc[r]);
            acc[r] = fmaf(u.z, w2, acc[r]);
            acc[r] = fmaf(u.w, w3, acc[r]);
        }
    }
#pragma unroll
    for (int r = 0; r < 12; r++) ppart[wid][r][lane] = acc[r];
    __syncthreads();
    for (int idx = tid; idx < 12 * 32; idx += 256) {
        int r = idx >> 5, l = idx & 31;
        float v = ppart[0][r][l];
#pragma unroll
        for (int j = 1; j < 8; j++) v += ppart[j][r][l];   // fixed order
        g_Wc[(row0 + r) * 32 + l] = v;
    }

    // bc on CTA 0: warps 0-3 x 256-k partials, fixed-order reduce
    if (blockIdx.x == 0) {
        if (wid < 4) {
            float pacc = 0.f;
            const int kbb = wid * 256;
#pragma unroll 8
            for (int kk = 0; kk < 256; kk++)
                pacc = fmaf(b1[kbb + kk], w23s[(kbb + kk) * 32 + lane], pacc);
            bpart[wid][lane] = pacc;
        }
        __syncthreads();
        if (wid == 0) {
            float bacc = g_b23[lane];
#pragma unroll
            for (int w = 0; w < 4; w++) bacc += bpart[w][lane];
            g_bc[lane] = bacc;
        }
    }
}

// ======================= stage 3: fused gather + pq + logits + loss + final =======================
// grid 128, 512thr: 16 warps = 2 row-groups(8 rows) x 8 K-slices (96k each)
__global__ __launch_bounds__(512) void k_main(const float* __restrict__ te,
                                              const int* __restrict__ pos,
                                              const float* __restrict__ labels,
                                              const float* __restrict__ pooler,
                                              float* __restrict__ out, int out_size) {
    extern __shared__ float s[];
    float* wct = s;                   // [768*32]  96KB
    float* as  = s + H_ * 32;         // [16*768]  48KB
    __shared__ float ppart[16][8][32];
    __shared__ float pqs[16][32];
    __shared__ float sml[16][5];
    __shared__ float red[128][5];
    __shared__ unsigned s_done;
    const int tid = threadIdx.x;
    const int wid = tid >> 5, lane = tid & 31;
    const int r0 = blockIdx.x * 16;
    const int batch = blockIdx.x >> 1;

    {
        const uint32_t sa = smem_u32(wct);
        const float* g = g_Wc;
#pragma unroll
        for (int j = 0; j < 12; j++) {           // 6144 cp16
            int c = tid + j * 512;
            CP16(sa + (uint32_t)c * 16, g + c * 4);
        }
        const uint32_t sb = smem_u32(as);
#pragma unroll
        for (int j = 0; j < 6; j++) {            // 3072 cp16 (192 per row)
            int c = tid + j * 512;
            int row = c / 192, ch = c % 192;
            const float* src = te + ((size_t)batch * S_ + pos[r0 + row]) * H_ + ch * 4;
            CP16(sb + (uint32_t)(row * H_ + ch * 4) * 4, src);
        }
        CP_COMMIT();
    }

    // pq overlapped with staging (global/L2 reads only): 16 warps x 48-k
    {
        const float* wcb = g_Wc + H_ * 32;
        const float* prow = pooler + (size_t)batch * H_;
        const int kb = wid * 48;
        float pacc = 0.f;
#pragma unroll
        for (int kk = 0; kk < 48; kk += 4) {
            float4 a4 = *(const float4*)&prow[kb + kk];
            pacc = fmaf(a4.x, wcb[(kb + kk + 0) * 32 + lane], pacc);
            pacc = fmaf(a4.y, wcb[(kb + kk + 1) * 32 + lane], pacc);
            pacc = fmaf(a4.z, wcb[(kb + kk + 2) * 32 + lane], pacc);
            pacc = fmaf(a4.w, wcb[(kb + kk + 3) * 32 + lane], pacc);
        }
        pqs[wid][lane] = pacc;
    }
    CP_WAIT0();
    __syncthreads();
    float pqv = g_bc[lane];
#pragma unroll
    for (int w = 0; w < 16; w++) pqv += pqs[w][lane];   // fixed order

    // warp wid: rg = wid&1 (8 rows), kh = wid>>1 (K slice of 96)
    const int rg = wid & 1, kh = wid >> 1;
    const int kb = kh * 96;
    float acc[8];
#pragma unroll
    for (int r = 0; r < 8; r++) acc[r] = 0.f;
#pragma unroll 2
    for (int k = 0; k < 96; k += 4) {
        float w0 = wct[(kb + k + 0) * 32 + lane];
        float w1 = wct[(kb + k + 1) * 32 + lane];
        float w2 = wct[(kb + k + 2) * 32 + lane];
        float w3 = wct[(kb + k + 3) * 32 + lane];
#pragma unroll
        for (int r = 0; r < 8; r++) {
            float4 u = *(const float4*)&as[(rg * 8 + r) * H_ + kb + k];
            acc[r] = fmaf(u.x, w0, acc[r]);
            acc[r] = fmaf(u.y, w1, acc[r]);
            acc[r] = fmaf(u.z, w2, acc[r]);
            acc[r] = fmaf(u.w, w3, acc[r]);
        }
    }
#pragma unroll
    for (int r = 0; r < 8; r++) ppart[wid][r][lane] = acc[r];
    __syncthreads();

    // warp wid handles row wid: combine 8 K-slices + pq, then loss
    const int rrg = wid >> 3, rr = wid & 7;
    float x = ppart[0 * 2 + rrg][rr][lane];
#pragma unroll
    for (int j = 1; j < 8; j++) x += ppart[j * 2 + rrg][rr][lane];  // fixed order
    x += pqv;

    const bool active = (lane < L_);
    const int gr = r0 + rrg * 8 + rr;
    float y = active ? labels[(size_t)gr * L_ + lane] : -1.0f;

    unsigned ball_bin  = __ballot_sync(0xffffffffu, active && (x > 0.f));
    unsigned ball_one  = __ballot_sync(0xffffffffu, active && (y > 0.5f));
    unsigned ball_real = __ballot_sync(0xffffffffu, active && (y != -1.0f));

    float sp  = fmaxf(x, 0.f) + log1pf(expf(-fabsf(x)));
    float bce = active ? (sp - x * y) : 0.f;
#pragma unroll
    for (int o = 16; o; o >>= 1) bce += __shfl_xor_sync(0xffffffffu, bce, o);

    if (lane == 0) {
        float mf = (ball_real != 0u) ? 1.f : 0.f;
        int co = __popc(ball_bin);
        int cl = __popc(ball_one);
        float cd = (float)(co - cl);
        bool eq = (mf != 0.f) && (co == 1) && (cl == 1);
        float pd = eq ? (float)(__ffs(ball_bin) - __ffs(ball_one)) : 0.f;
        sml[wid][0] = mf * bce;
        sml[wid][1] = mf;
        sml[wid][2] = mf * cd * cd;
        sml[wid][3] = pd * pd;
        sml[wid][4] = eq ? 1.f : 0.f;
    }
    __syncthreads();
    if (tid < 5) {
        float ssum = 0.f;
        for (int w = 0; w < 16; w++) ssum += sml[w][tid];   // fixed order
        g_part[blockIdx.x * 5 + tid] = ssum;
    }

    // ---- last-block final reduction (deterministic fixed-order tree) ----
    __threadfence();
    __syncthreads();
    if (tid == 0) s_done = atomicAdd(&g_done, 1u);
    __syncthreads();
    if (s_done == 127u) {
        __threadfence();
        if (tid < 128)
            for (int c = 0; c < 5; c++) red[tid][c] = g_part[tid * 5 + c];
        __syncthreads();
        for (int st = 64; st > 0; st >>= 1) {
            if (tid < st)
                for (int c = 0; c < 5; c++) red[tid][c] += red[tid + st][c];
            __syncthreads();
        }
        if (tid == 0) {
            float bce_loss   = red[0][0] / (red[0][1] * (float)L_);
            float count_loss = red[0][2] / (float)MROWS;
            float pos_loss   = (red[0][4] > 0.f) ? (red[0][3] / red[0][4]) : 0.f;
            float loss = bce_loss + 10.f * count_loss + 5.f * pos_loss;
            for (int i = 0; i < out_size; i++) out[i] = loss;
        }
    }
}

// ======================= launch =======================
extern "C" void kernel_launch(void* const* d_in, const int* in_sizes, int n_in,
                              void* d_out, int out_size)
{
    const float* te   = (const float*)d_in[0];
    const float* pool = (const float*)d_in[1];
    const int*   pos  = (const int*)  d_in[2];
    const float* lab  = (const float*)d_in[3];
    const float* W1   = (const float*)d_in[4];
    const float* b1   = (const float*)d_in[5];
    const float* W2   = (const float*)d_in[6];
    const float* b2   = (const float*)d_in[7];
    const float* W3   = (const float*)d_in[8];
    const float* b3   = (const float*)d_in[9];

    const int SM_W23  = (512 * 30 + 8 + 8 * 512) * 4;   //  77856
    const int SM_WC   = (FH_ * 32 + 12 * FH_) * 4;      // 180224
    const int SM_MAIN = (H_ * 32 + 16 * H_) * 4;        // 147456

    cudaFuncSetAttribute(k_w23,  cudaFuncAttributeMaxDynamicSharedMemorySize, SM_W23);
    cudaFuncSetAttribute(k_wc,   cudaFuncAttributeMaxDynamicSharedMemorySize, SM_WC);
    cudaFuncSetAttribute(k_main, cudaFuncAttributeMaxDynamicSharedMemorySize, SM_MAIN);

    k_w23<<<FH_ / 8, 512, SM_W23>>>(W2, W3, b2, b3);    // W23, b23 (+reset counter)
    k_wc<<<(2 * H_) / 12, 256, SM_WC>>>(W1, b1);        // Wc, bc
    k_main<<<MROWS / 16, 512, SM_MAIN>>>(te, pos, lab, pool,
                                         (float*)d_out, out_size);
}